// round 2
// baseline (speedup 1.0000x reference)
#include <cuda_runtime.h>

// Problem constants
#define EMB   400
#define HID   300
#define KEY   128
#define VALD  128
#define VOCAB 33
#define TT    256
#define BB    256
#define SS    512

#define KCAT  828            // EMB + VALD + HID
#define KPAD  832            // padded K (multiple of 16)
#define MROWS 1200           // 4*HID gate rows
#define MPAD  1216           // padded rows (multiple of 32)

// ---------------- device scratch (static globals; no allocation) ----------------
__device__ float g_WcatT[KPAD * MPAD];   // [k][r]  transposed concatenated weights (~4MB)
__device__ float g_Z[KPAD * BB];         // [k][b]  GEMM rhs: [emb; ctx; h] per column
__device__ float g_gates[BB * MPAD];     // [b][r]  GEMM output (transposed for K2 reads)
__device__ float g_c[BB * HID];          // cell state

// ---------------- helpers ----------------
__device__ __forceinline__ float warp_sum(float v) {
#pragma unroll
    for (int m = 16; m > 0; m >>= 1) v += __shfl_xor_sync(0xffffffffu, v, m);
    return v;
}
__device__ __forceinline__ float warp_max(float v) {
#pragma unroll
    for (int m = 16; m > 0; m >>= 1) v = fmaxf(v, __shfl_xor_sync(0xffffffffu, v, m));
    return v;
}
__device__ __forceinline__ float sigf(float x) { return 1.0f / (1.0f + __expf(-x)); }

// packed f32x2 FMA (Blackwell): 2 fp32 MACs per instruction, fp32-exact
__device__ __forceinline__ unsigned long long fma2(unsigned long long a,
                                                   unsigned long long b,
                                                   unsigned long long c) {
    unsigned long long d;
    asm("fma.rn.f32x2 %0, %1, %2, %3;" : "=l"(d) : "l"(a), "l"(b), "l"(c));
    return d;
}
__device__ __forceinline__ unsigned long long pack2(float x) {
    unsigned long long d;
    unsigned int xi = __float_as_uint(x);
    asm("mov.b64 %0, {%1, %1};" : "=l"(d) : "r"(xi));
    return d;
}
__device__ __forceinline__ float2 unpack2(unsigned long long v) {
    unsigned int lo, hi;
    asm("mov.b64 {%0, %1}, %2;" : "=r"(lo), "=r"(hi) : "l"(v));
    return make_float2(__uint_as_float(lo), __uint_as_float(hi));
}

// ---------------- prep: build transposed padded weight matrix, zero Z pad rows ----------------
__global__ void __launch_bounds__(256) kprep(const float* __restrict__ W_ih,
                                             const float* __restrict__ W_hh) {
    int stride = gridDim.x * blockDim.x;
    int idx = blockIdx.x * blockDim.x + threadIdx.x;
    const int total = KPAD * MPAD;
    for (int i = idx; i < total; i += stride) {
        int k = i / MPAD;
        int r = i % MPAD;
        float v = 0.0f;
        if (r < MROWS) {
            if (k < EMB + VALD)      v = W_ih[r * (EMB + VALD) + k];
            else if (k < KCAT)       v = W_hh[r * HID + (k - (EMB + VALD))];
        }
        g_WcatT[i] = v;
    }
    // zero the padded Z rows [KCAT, KPAD)
    if (idx < (KPAD - KCAT) * BB) g_Z[KCAT * BB + idx] = 0.0f;
}

// ---------------- attention (shared by K0 and K2); block = one batch column ----------------
__device__ void attention_block(int b, int tid,
                                const float* __restrict__ keys,
                                const float* __restrict__ values,
                                const float* __restrict__ phi_w,
                                const float* __restrict__ phi_b,
                                const float* h_s, float* q_s, float* e_s,
                                float* ctx_s, float* ctx2_s, float* red_s) {
    int warp = tid >> 5, lane = tid & 31;

    // q = phi_w @ h + phi_b     (warp per output, lanes split HID, coalesced phi_w reads)
    for (int kq = warp; kq < KEY; kq += 8) {
        float s = 0.0f;
        for (int j = lane; j < HID; j += 32) s += phi_w[kq * HID + j] * h_s[j];
        s = warp_sum(s);
        if (lane == 0) q_s[kq] = s + phi_b[kq];
    }
    __syncthreads();

    // energy[s] = q . keys[s,b,:]   (warp per s; lane owns 4 contiguous k -> LDG.128)
    float4 qv = *(const float4*)&q_s[lane * 4];
#pragma unroll 4
    for (int s0 = warp; s0 < SS; s0 += 8) {
        float4 kv = *(const float4*)&keys[((size_t)s0 * BB + b) * KEY + lane * 4];
        float e = qv.x * kv.x + qv.y * kv.y + qv.z * kv.z + qv.w * kv.w;
        e = warp_sum(e);
        if (lane == 0) e_s[s0] = e;
    }
    __syncthreads();

    // softmax over SS
    float m = -3.0e38f;
    for (int s = tid; s < SS; s += 256) m = fmaxf(m, e_s[s]);
    m = warp_max(m);
    if (lane == 0) red_s[warp] = m;
    __syncthreads();
    float mf = red_s[0];
#pragma unroll
    for (int i = 1; i < 8; i++) mf = fmaxf(mf, red_s[i]);
    __syncthreads();                 // all reads of red_s(max) done before reuse

    float sum = 0.0f;
    for (int s = tid; s < SS; s += 256) {
        float v = __expf(e_s[s] - mf);
        e_s[s] = v;
        sum += v;
    }
    sum = warp_sum(sum);
    if (lane == 0) red_s[warp] = sum;
    __syncthreads();
    float tot = red_s[0];
#pragma unroll
    for (int i = 1; i < 8; i++) tot += red_s[i];
    float inv = 1.0f / tot;
    for (int s = tid; s < SS; s += 256) e_s[s] *= inv;   // own indices only, no race
    __syncthreads();

    // ctx[d] = sum_s att[s] * values[s,b,d]   (tid<128: s in [0,256); else [256,512))
    int d  = tid & 127;
    int sh = (tid >> 7) * 256;
    float acc = 0.0f;
#pragma unroll 8
    for (int s = 0; s < 256; s++) {
        acc = fmaf(e_s[sh + s], values[((size_t)(sh + s) * BB + b) * VALD + d], acc);
    }
    if (tid < 128) ctx_s[d] = acc; else ctx2_s[d] = acc;
    __syncthreads();
    if (tid < 128) ctx_s[d] += ctx2_s[d];
    __syncthreads();
}

__device__ void assemble_Z(int b, int tid, int tok,
                           const float* __restrict__ embedding,
                           const float* ctx_s, const float* h_s) {
    for (int e = tid; e < EMB; e += 256)  g_Z[e * BB + b] = embedding[tok * EMB + e];
    for (int d = tid; d < VALD; d += 256) g_Z[(EMB + d) * BB + b] = ctx_s[d];
    for (int j = tid; j < HID; j += 256)  g_Z[(EMB + VALD + j) * BB + b] = h_s[j];
}

// ---------------- K0: init state, ctx0 = attend(h0), assemble Z for t=0 ----------------
__global__ void __launch_bounds__(256) k0_init(const float* __restrict__ keys,
                                               const float* __restrict__ values,
                                               const float* __restrict__ embedding,
                                               const int*   __restrict__ input,
                                               const float* __restrict__ phi_w,
                                               const float* __restrict__ phi_b,
                                               const float* __restrict__ h0,
                                               const float* __restrict__ c0) {
    __shared__ __align__(16) float h_s[HID];
    __shared__ __align__(16) float q_s[KEY];
    __shared__ __align__(16) float e_s[SS];
    __shared__ __align__(16) float ctx_s[VALD];
    __shared__ __align__(16) float ctx2_s[VALD];
    __shared__ float red_s[8];
    int b = blockIdx.x, tid = threadIdx.x;

    for (int j = tid; j < HID; j += 256) {
        h_s[j] = h0[j];                 // h0 is [1,HID], broadcast over batch
        g_c[b * HID + j] = c0[j];
    }
    __syncthreads();

    attention_block(b, tid, keys, values, phi_w, phi_b, h_s, q_s, e_s, ctx_s, ctx2_s, red_s);

    int tok = input[b];                 // input[0][b]
    assemble_Z(b, tid, tok, embedding, ctx_s, h_s);
}

// ---------------- K1: gates GEMM  gates[b][r] = sum_k WcatT[k][r] * Z[k][b] ----------------
// grid (38, 4): tile TM=32 rows x TN=64 cols; 256 threads; thread = 2 rows x 4 cols (f32x2)
__global__ void __launch_bounds__(256) k1_gemm() {
    __shared__ __align__(16) float Ws[16][32];
    __shared__ __align__(16) float Zs[16][64];
    int tid = threadIdx.x;
    int rowBase = blockIdx.x * 32;
    int colBase = blockIdx.y * 64;
    int rg = tid & 15, cg = tid >> 4;
    int r0 = rg * 2, c0 = cg * 4;

    int wk = tid >> 3, wr = (tid & 7) << 2;   // W stage (tid < 128)
    int zk = tid >> 4, zc = (tid & 15) << 2;  // Z stage

    float4 wbuf = make_float4(0, 0, 0, 0), zbuf;
    if (tid < 128)
        wbuf = *(const float4*)&g_WcatT[(size_t)wk * MPAD + rowBase + wr];
    zbuf = *(const float4*)&g_Z[zk * BB + colBase + zc];

    unsigned long long a00 = 0ull, a01 = 0ull, a10 = 0ull, a11 = 0ull;

    const int NKT = KPAD / 16;   // 52
    for (int kt = 0; kt < NKT; kt++) {
        __syncthreads();
        if (tid < 128) *(float4*)&Ws[wk][wr] = wbuf;
        *(float4*)&Zs[zk][zc] = zbuf;
        __syncthreads();
        if (kt + 1 < NKT) {
            int kb = (kt + 1) * 16;
            if (tid < 128)
                wbuf = *(const float4*)&g_WcatT[(size_t)(kb + wk) * MPAD + rowBase + wr];
            zbuf = *(const float4*)&g_Z[(kb + zk) * BB + colBase + zc];
        }
#pragma unroll
        for (int k = 0; k < 16; k++) {
            float2 w2 = *(const float2*)&Ws[k][r0];
            ulonglong2 zz = *(const ulonglong2*)&Zs[k][c0];
            unsigned long long w0 = pack2(w2.x), w1 = pack2(w2.y);
            a00 = fma2(w0, zz.x, a00);
            a01 = fma2(w0, zz.y, a01);
            a10 = fma2(w1, zz.x, a10);
            a11 = fma2(w1, zz.y, a11);
        }
    }

    float2 v00 = unpack2(a00), v01 = unpack2(a01);
    float2 v10 = unpack2(a10), v11 = unpack2(a11);
    int r = rowBase + r0;
    int c = colBase + c0;
    *(float2*)&g_gates[(size_t)(c + 0) * MPAD + r] = make_float2(v00.x, v10.x);
    *(float2*)&g_gates[(size_t)(c + 1) * MPAD + r] = make_float2(v00.y, v10.y);
    *(float2*)&g_gates[(size_t)(c + 2) * MPAD + r] = make_float2(v01.x, v11.x);
    *(float2*)&g_gates[(size_t)(c + 3) * MPAD + r] = make_float2(v01.y, v11.y);
}

// ---------------- K2: cell update, logits (uses OLD ctx), attention, assemble next Z ----------
__global__ void __launch_bounds__(256) k2_step(const float* __restrict__ keys,
                                               const float* __restrict__ values,
                                               const float* __restrict__ embedding,
                                               const int*   __restrict__ input,
                                               const float* __restrict__ phi_w,
                                               const float* __restrict__ phi_b,
                                               const float* __restrict__ proj_w,
                                               const float* __restrict__ proj_b,
                                               const float* __restrict__ b_ih,
                                               const float* __restrict__ b_hh,
                                               float* __restrict__ out, int t) {
    __shared__ __align__(16) float h_s[HID];
    __shared__ __align__(16) float q_s[KEY];
    __shared__ __align__(16) float e_s[SS];
    __shared__ __align__(16) float ctx_s[VALD];
    __shared__ __align__(16) float ctx2_s[VALD];
    __shared__ __align__(16) float ctxo_s[VALD];
    __shared__ float red_s[8];
    int b = blockIdx.x, tid = threadIdx.x;
    int warp = tid >> 5, lane = tid & 31;

    // previous ctx lives in Z rows [EMB, EMB+VALD)
    for (int d = tid; d < VALD; d += 256) ctxo_s[d] = g_Z[(EMB + d) * BB + b];

    // LSTM cell update
    const float* g = &g_gates[(size_t)b * MPAD];
    for (int j = tid; j < HID; j += 256) {
        float gi = g[j]            + b_ih[j]           + b_hh[j];
        float gf = g[HID + j]      + b_ih[HID + j]     + b_hh[HID + j];
        float gg = g[2 * HID + j]  + b_ih[2 * HID + j] + b_hh[2 * HID + j];
        float go = g[3 * HID + j]  + b_ih[3 * HID + j] + b_hh[3 * HID + j];
        float cc = sigf(gf) * g_c[b * HID + j] + sigf(gi) * tanhf(gg);
        float hh = sigf(go) * tanhf(cc);
        g_c[b * HID + j] = cc;
        h_s[j] = hh;
    }
    __syncthreads();

    // logits = [h_new, ctx_old] @ proj_w.T + proj_b
    for (int v = warp; v < VOCAB; v += 8) {
        float s = 0.0f;
        for (int j = lane; j < HID + VALD; j += 32) {
            float x = (j < HID) ? h_s[j] : ctxo_s[j - HID];
            s += proj_w[v * (HID + VALD) + j] * x;
        }
        s = warp_sum(s);
        if (lane == 0) out[((size_t)t * BB + b) * VOCAB + v] = s + proj_b[v];
    }

    // new ctx = attend(h_new)
    attention_block(b, tid, keys, values, phi_w, phi_b, h_s, q_s, e_s, ctx_s, ctx2_s, red_s);

    if (t < TT - 1) {
        int tok = input[(size_t)(t + 1) * BB + b];
        assemble_Z(b, tid, tok, embedding, ctx_s, h_s);
    }
}

// ---------------- launch ----------------
extern "C" void kernel_launch(void* const* d_in, const int* in_sizes, int n_in,
                              void* d_out, int out_size) {
    const int*   input     = (const int*)  d_in[0];
    const float* keys      = (const float*)d_in[1];
    const float* values    = (const float*)d_in[2];
    const float* embedding = (const float*)d_in[3];
    const float* phi_w     = (const float*)d_in[4];
    const float* phi_b     = (const float*)d_in[5];
    const float* h0        = (const float*)d_in[6];
    const float* c0        = (const float*)d_in[7];
    const float* W_ih      = (const float*)d_in[8];
    const float* b_ih      = (const float*)d_in[9];
    const float* W_hh      = (const float*)d_in[10];
    const float* b_hh      = (const float*)d_in[11];
    const float* proj_w    = (const float*)d_in[12];
    const float* proj_b    = (const float*)d_in[13];
    float* out = (float*)d_out;

    kprep<<<256, 256>>>(W_ih, W_hh);
    k0_init<<<BB, 256>>>(keys, values, embedding, input, phi_w, phi_b, h0, c0);

    dim3 g1(MPAD / 32, BB / 64);   // (38, 4)
    for (int t = 0; t < TT; t++) {
        k1_gemm<<<g1, 256>>>();
        k2_step<<<BB, 256>>>(keys, values, embedding, input, phi_w, phi_b,
                             proj_w, proj_b, b_ih, b_hh, out, t);
    }
}

// round 3
// speedup vs baseline: 1.7197x; 1.7197x over previous
#include <cuda_runtime.h>

#define EMB   400
#define HID   300
#define KEY   128
#define VALD  128
#define VOCAB 33
#define TT    256
#define BB    256
#define SS    512

#define KP2   432          // GEMM K: ctx(128) + h(300) + pad(4)
#define MROWS 1200
#define MPAD  1216
#define NBLK  256
#define GTILES 152         // 38 row-tiles x 4 col-tiles

// ---------------- device scratch ----------------
__device__ float g_Wdup[(size_t)KP2 * 2 * MPAD];          // [k][2*r] duplicated weights (4.2MB)
__device__ float g_Z[KP2 * BB];                           // [k][b]: rows 0-127 ctx, 128-427 h
__device__ float g_gmm[BB * MPAD];                        // [b][r] gemm out
__device__ float g_c[BB * HID];                           // cell state
__device__ float g_gv[VOCAB * MPAD];                      // W_emb@emb[v] + b_ih + b_hh
__device__ float g_phiT[HID * KEY];                       // [j][kq]
__device__ float g_keysT[(size_t)BB * KEY * SS];          // [b][k][s]  (67MB)
__device__ float g_valsT[(size_t)BB * SS * VALD];         // [b][s][d]  (67MB)
__device__ unsigned g_cnt;
__device__ unsigned g_gen;

// ---------------- helpers ----------------
__device__ __forceinline__ float warp_sum(float v) {
#pragma unroll
    for (int m = 16; m > 0; m >>= 1) v += __shfl_xor_sync(0xffffffffu, v, m);
    return v;
}
__device__ __forceinline__ float warp_max(float v) {
#pragma unroll
    for (int m = 16; m > 0; m >>= 1) v = fmaxf(v, __shfl_xor_sync(0xffffffffu, v, m));
    return v;
}
__device__ __forceinline__ float sigf(float x) { return 1.0f / (1.0f + __expf(-x)); }

__device__ __forceinline__ unsigned long long fma2(unsigned long long a,
                                                   unsigned long long b,
                                                   unsigned long long c) {
    unsigned long long d;
    asm("fma.rn.f32x2 %0, %1, %2, %3;" : "=l"(d) : "l"(a), "l"(b), "l"(c));
    return d;
}
__device__ __forceinline__ float2 unpack2(unsigned long long v) {
    unsigned int lo, hi;
    asm("mov.b64 {%0, %1}, %2;" : "=r"(lo), "=r"(hi) : "l"(v));
    return make_float2(__uint_as_float(lo), __uint_as_float(hi));
}

// grid barrier: release (threadfence=CCTL.IVALL) + counter + acquire fence
__device__ __forceinline__ void gsync() {
    __syncthreads();
    if (threadIdx.x == 0) {
        __threadfence();                       // release my writes
        volatile unsigned* vg = &g_gen;
        unsigned my = *vg;
        if (atomicAdd(&g_cnt, 1u) == NBLK - 1u) {
            atomicExch(&g_cnt, 0u);
            __threadfence();
            *vg = my + 1u;
        } else {
            while (*vg == my) { }
        }
        __threadfence();                       // acquire: invalidate L1
    }
    __syncthreads();
}

// ---------------- prep kernels ----------------
__global__ void __launch_bounds__(256) kprep_w(const float* __restrict__ W_ih,
                                               const float* __restrict__ W_hh,
                                               const float* __restrict__ phi_w) {
    int idx = blockIdx.x * blockDim.x + threadIdx.x;
    int stride = gridDim.x * blockDim.x;
    for (int i = idx; i < KP2 * MPAD; i += stride) {
        int k = i / MPAD, r = i % MPAD;
        float v = 0.0f;
        if (r < MROWS) {
            if (k < VALD)            v = W_ih[r * (EMB + VALD) + EMB + k];   // ctx cols
            else if (k < VALD + HID) v = W_hh[r * HID + (k - VALD)];         // h cols
        }
        g_Wdup[(size_t)k * (2 * MPAD) + 2 * r]     = v;
        g_Wdup[(size_t)k * (2 * MPAD) + 2 * r + 1] = v;
    }
    for (int i = idx; i < HID * KEY; i += stride) {
        int j = i / KEY, kq = i % KEY;
        g_phiT[i] = phi_w[kq * HID + j];
    }
    for (int i = idx; i < (KP2 - (VALD + HID)) * BB; i += stride)
        g_Z[(VALD + HID) * BB + i] = 0.0f;     // zero pad rows of Z (never rewritten)
}

__global__ void __launch_bounds__(256) kprep_vocab(const float* __restrict__ W_ih,
                                                   const float* __restrict__ embedding,
                                                   const float* __restrict__ b_ih,
                                                   const float* __restrict__ b_hh) {
    __shared__ float emb[EMB];
    int v = blockIdx.x;
    for (int e = threadIdx.x; e < EMB; e += 256) emb[e] = embedding[v * EMB + e];
    __syncthreads();
    for (int r = threadIdx.x; r < MPAD; r += 256) {
        float s = 0.0f;
        if (r < MROWS) {
            s = b_ih[r] + b_hh[r];
            const float* wr = &W_ih[(size_t)r * (EMB + VALD)];
#pragma unroll 4
            for (int e = 0; e < EMB; e++) s += wr[e] * emb[e];
        }
        g_gv[v * MPAD + r] = s;
    }
}

__global__ void __launch_bounds__(256) kprep_keys(const float* __restrict__ keys) {
    __shared__ float ts[64][129];
    int s0 = blockIdx.x * 64;      // 8 s-blocks
    int b  = blockIdx.y;           // 256
    int tid = threadIdx.x;
#pragma unroll
    for (int p = 0; p < 8; p++) {
        int i  = p * 8 + (tid >> 5);
        int k4 = (tid & 31) * 4;
        float4 v = *(const float4*)&keys[((size_t)(s0 + i) * BB + b) * KEY + k4];
        ts[i][k4] = v.x; ts[i][k4 + 1] = v.y; ts[i][k4 + 2] = v.z; ts[i][k4 + 3] = v.w;
    }
    __syncthreads();
#pragma unroll
    for (int p = 0; p < 8; p++) {
        int k  = p * 16 + (tid >> 4);
        int s4 = (tid & 15) * 4;
        float4 v = make_float4(ts[s4][k], ts[s4 + 1][k], ts[s4 + 2][k], ts[s4 + 3][k]);
        *(float4*)&g_keysT[((size_t)b * KEY + k) * SS + s0 + s4] = v;
    }
}

__global__ void __launch_bounds__(256) kprep_vals(const float* __restrict__ values) {
    int s0 = blockIdx.x * 64;
    int b  = blockIdx.y;
    int tid = threadIdx.x;
#pragma unroll
    for (int p = 0; p < 8; p++) {
        int e = p * 256 + tid;
        int row = e >> 5;
        int c4 = (e & 31) * 4;
        float4 v = *(const float4*)&values[((size_t)(s0 + row) * BB + b) * VALD + c4];
        *(float4*)&g_valsT[((size_t)b * SS + s0 + row) * VALD + c4] = v;
    }
}

// ---------------- attention: block = one batch column ----------------
__device__ void attention(int b, int tid,
                          const float* __restrict__ phi_b,
                          const float* h_s, float* q_s, float* qp,
                          float* e_s, float* part, float* ctx_s, float* red_s) {
    int warp = tid >> 5, lane = tid & 31;

    // q[kq] = phi_wT(:,kq) . h + phi_b[kq]   (128 kq x 2 j-halves)
    {
        int kq = tid & 127;
        int half = tid >> 7;
        const float* pw = &g_phiT[(size_t)(half * 150) * KEY + kq];
        const float* hh = &h_s[half * 150];
        float acc = 0.0f;
#pragma unroll 10
        for (int j = 0; j < 150; j++) acc = fmaf(pw[(size_t)j * KEY], hh[j], acc);
        qp[tid] = acc;
    }
    __syncthreads();
    if (tid < KEY) q_s[tid] = qp[tid] + qp[tid + 128] + phi_b[tid];
    __syncthreads();

    // energy: thread owns 2 consecutive s, loops k with broadcast q
    {
        int s0 = tid * 2;
        const float2* kp = (const float2*)&g_keysT[(size_t)b * KEY * SS + s0];
        float e0 = 0.0f, e1 = 0.0f;
#pragma unroll 8
        for (int k = 0; k < KEY; k++) {
            float2 kv = kp[(size_t)k * (SS / 2)];
            float qk = q_s[k];
            e0 = fmaf(qk, kv.x, e0);
            e1 = fmaf(qk, kv.y, e1);
        }
        e_s[s0] = e0; e_s[s0 + 1] = e1;
    }
    __syncthreads();

    // softmax over SS
    float m = -3.0e38f;
    for (int s = tid; s < SS; s += 256) m = fmaxf(m, e_s[s]);
    m = warp_max(m);
    if (lane == 0) red_s[warp] = m;
    __syncthreads();
    float mf = red_s[0];
#pragma unroll
    for (int i = 1; i < 8; i++) mf = fmaxf(mf, red_s[i]);
    __syncthreads();
    float sum = 0.0f;
    for (int s = tid; s < SS; s += 256) {
        float v = __expf(e_s[s] - mf);
        e_s[s] = v;
        sum += v;
    }
    sum = warp_sum(sum);
    if (lane == 0) red_s[warp] = sum;
    __syncthreads();
    float tot = red_s[0];
#pragma unroll
    for (int i = 1; i < 8; i++) tot += red_s[i];
    float inv = 1.0f / tot;
    for (int s = tid; s < SS; s += 256) e_s[s] *= inv;
    __syncthreads();

    // ctx: warp w handles s in [w*64,(w+1)*64), lane owns 4 d (float4 loads)
    {
        float4 acc = make_float4(0, 0, 0, 0);
        int sbase = warp * 64;
        const float4* vp = (const float4*)&g_valsT[((size_t)b * SS + sbase) * VALD + lane * 4];
#pragma unroll 8
        for (int i = 0; i < 64; i++) {
            float a = e_s[sbase + i];
            float4 vv = vp[(size_t)i * (VALD / 4)];
            acc.x = fmaf(a, vv.x, acc.x);
            acc.y = fmaf(a, vv.y, acc.y);
            acc.z = fmaf(a, vv.z, acc.z);
            acc.w = fmaf(a, vv.w, acc.w);
        }
        *(float4*)&part[warp * VALD + lane * 4] = acc;
    }
    __syncthreads();
    if (tid < VALD) {
        float s = 0.0f;
#pragma unroll
        for (int w = 0; w < 8; w++) s += part[w * VALD + tid];
        ctx_s[tid] = s;
    }
    __syncthreads();
}

// ---------------- persistent main kernel ----------------
__global__ void __launch_bounds__(256, 2) kmain(const int* __restrict__ input,
                                                const float* __restrict__ phi_b,
                                                const float* __restrict__ h0,
                                                const float* __restrict__ c0,
                                                const float* __restrict__ proj_w,
                                                const float* __restrict__ proj_b,
                                                float* __restrict__ out) {
    __shared__ float h_s[HID];
    __shared__ float q_s[KEY];
    __shared__ float qp[256];
    __shared__ float e_s[SS];
    __shared__ __align__(16) float part[8 * VALD];
    __shared__ float ctx_s[VALD];
    __shared__ float ctxo_s[VALD];
    __shared__ float red_s[8];
    __shared__ __align__(16) float Ws[16 * 64];
    __shared__ __align__(16) float Zs[16 * 64];

    int bid = blockIdx.x, tid = threadIdx.x;
    int warp = tid >> 5, lane = tid & 31;
    int b = bid;

    // ---- init: h=h0, c=c0, ctx0=attend(h0), assemble Z ----
    for (int j = tid; j < HID; j += 256) {
        h_s[j] = h0[j];
        g_c[b * HID + j] = c0[j];
    }
    __syncthreads();
    attention(b, tid, phi_b, h_s, q_s, qp, e_s, part, ctx_s, red_s);
    for (int d = tid; d < VALD; d += 256) g_Z[d * BB + b] = ctx_s[d];
    for (int j = tid; j < HID; j += 256)  g_Z[(VALD + j) * BB + b] = h_s[j];
    gsync();

    for (int t = 0; t < TT; t++) {
        // ---- phase G: GEMM gates = Wcat @ Z  (152 tiles, 32r x 64c) ----
        if (bid < GTILES) {
            int rowBase = (bid % 38) * 32;
            int colBase = (bid / 38) * 64;
            int rg = tid & 15, cg = tid >> 4;
            int sk = tid >> 4, soff = (tid & 15) * 4;

            float4 wbuf = *(const float4*)&g_Wdup[(size_t)sk * (2 * MPAD) + rowBase * 2 + soff];
            float4 zbuf = *(const float4*)&g_Z[sk * BB + colBase + soff];

            unsigned long long a00 = 0, a01 = 0, a10 = 0, a11 = 0;
            const int NKT = KP2 / 16;   // 27
            for (int kt = 0; kt < NKT; kt++) {
                __syncthreads();
                *(float4*)&Ws[sk * 64 + soff] = wbuf;
                *(float4*)&Zs[sk * 64 + soff] = zbuf;
                __syncthreads();
                if (kt + 1 < NKT) {
                    int kb = (kt + 1) * 16;
                    wbuf = *(const float4*)&g_Wdup[(size_t)(kb + sk) * (2 * MPAD) + rowBase * 2 + soff];
                    zbuf = *(const float4*)&g_Z[(kb + sk) * BB + colBase + soff];
                }
#pragma unroll
                for (int k = 0; k < 16; k++) {
                    ulonglong2 ww = *(const ulonglong2*)&Ws[k * 64 + rg * 4];
                    ulonglong2 zz = *(const ulonglong2*)&Zs[k * 64 + cg * 4];
                    a00 = fma2(ww.x, zz.x, a00);
                    a01 = fma2(ww.x, zz.y, a01);
                    a10 = fma2(ww.y, zz.x, a10);
                    a11 = fma2(ww.y, zz.y, a11);
                }
            }
            float2 v00 = unpack2(a00), v01 = unpack2(a01);
            float2 v10 = unpack2(a10), v11 = unpack2(a11);
            int r = rowBase + rg * 2;
            int c = colBase + cg * 4;
            *(float2*)&g_gmm[(size_t)(c + 0) * MPAD + r] = make_float2(v00.x, v10.x);
            *(float2*)&g_gmm[(size_t)(c + 1) * MPAD + r] = make_float2(v00.y, v10.y);
            *(float2*)&g_gmm[(size_t)(c + 2) * MPAD + r] = make_float2(v01.x, v11.x);
            *(float2*)&g_gmm[(size_t)(c + 3) * MPAD + r] = make_float2(v01.y, v11.y);
        }
        gsync();

        // ---- phase S: cell, logits, attention, Z assembly (block = batch b) ----
        int tok = input[t * BB + b];
        for (int d = tid; d < VALD; d += 256) ctxo_s[d] = g_Z[d * BB + b];   // old ctx

        const float* gm = &g_gmm[(size_t)b * MPAD];
        const float* gv = &g_gv[(size_t)tok * MPAD];
        for (int j = tid; j < HID; j += 256) {
            float gi = gm[j]           + gv[j];
            float gf = gm[HID + j]     + gv[HID + j];
            float gg = gm[2 * HID + j] + gv[2 * HID + j];
            float go = gm[3 * HID + j] + gv[3 * HID + j];
            float cc = sigf(gf) * g_c[b * HID + j] + sigf(gi) * tanhf(gg);
            float hh = sigf(go) * tanhf(cc);
            g_c[b * HID + j] = cc;
            h_s[j] = hh;
        }
        __syncthreads();

        // logits = [h_new, ctx_old] @ proj_w.T + proj_b
        for (int v = warp; v < VOCAB; v += 8) {
            float s = 0.0f;
            for (int j = lane; j < HID + VALD; j += 32) {
                float x = (j < HID) ? h_s[j] : ctxo_s[j - HID];
                s = fmaf(proj_w[v * (HID + VALD) + j], x, s);
            }
            s = warp_sum(s);
            if (lane == 0) out[((size_t)t * BB + b) * VOCAB + v] = s + proj_b[v];
        }

        attention(b, tid, phi_b, h_s, q_s, qp, e_s, part, ctx_s, red_s);

        for (int d = tid; d < VALD; d += 256) g_Z[d * BB + b] = ctx_s[d];
        for (int j = tid; j < HID; j += 256)  g_Z[(VALD + j) * BB + b] = h_s[j];
        gsync();
    }
}

// ---------------- launch ----------------
extern "C" void kernel_launch(void* const* d_in, const int* in_sizes, int n_in,
                              void* d_out, int out_size) {
    const int*   input     = (const int*)  d_in[0];
    const float* keys      = (const float*)d_in[1];
    const float* values    = (const float*)d_in[2];
    const float* embedding = (const float*)d_in[3];
    const float* phi_w     = (const float*)d_in[4];
    const float* phi_b     = (const float*)d_in[5];
    const float* h0        = (const float*)d_in[6];
    const float* c0        = (const float*)d_in[7];
    const float* W_ih      = (const float*)d_in[8];
    const float* b_ih      = (const float*)d_in[9];
    const float* W_hh      = (const float*)d_in[10];
    const float* b_hh      = (const float*)d_in[11];
    const float* proj_w    = (const float*)d_in[12];
    const float* proj_b    = (const float*)d_in[13];
    float* out = (float*)d_out;

    kprep_w<<<512, 256>>>(W_ih, W_hh, phi_w);
    kprep_vocab<<<VOCAB, 256>>>(W_ih, embedding, b_ih, b_hh);
    kprep_keys<<<dim3(8, BB), 256>>>(keys);
    kprep_vals<<<dim3(8, BB), 256>>>(values);
    kmain<<<NBLK, 256>>>(input, phi_b, h0, c0, proj_w, proj_b, out);
}

// round 4
// speedup vs baseline: 2.3103x; 1.3434x over previous
#include <cuda_runtime.h>
#include <cuda_fp16.h>

#define EMB   400
#define HID   300
#define HIDP  304          // padded for uint4 fp16 loads
#define KEY   128
#define VALD  128
#define VOCAB 33
#define TT    256
#define BB    256
#define SS    512

#define KP2   432          // GEMM K: ctx(128) + h(300) + pad(4)
#define MROWS 1200
#define MPAD  1216
#define NBLK  256
#define GTILES 152         // 38 row-tiles x 4 col-tiles

// ---------------- device scratch ----------------
__device__ float  g_Wdup[(size_t)KP2 * 2 * MPAD];         // duplicated weights (4.2MB)
__device__ float  g_Z[KP2 * BB];                          // [k][b]: ctx rows, h rows
__device__ float  g_gmm[BB * MPAD];                       // [b][r]
__device__ float  g_c[BB * HID];
__device__ float  g_gv[VOCAB * MPAD];                     // W_emb@emb[v] + biases
__device__ __half g_phiH[KEY * HIDP];                     // [kq][j] fp16 (78KB)
__device__ __half g_keysH[(size_t)BB * KEY * SS];         // [b][k][s] fp16 (33.5MB)
__device__ float  g_valsT[(size_t)BB * SS * VALD];        // [b][s][d] fp32 (67MB)
__device__ unsigned g_cnt;
__device__ unsigned g_gen;

// ---------------- helpers ----------------
__device__ __forceinline__ float warp_sum(float v) {
#pragma unroll
    for (int m = 16; m > 0; m >>= 1) v += __shfl_xor_sync(0xffffffffu, v, m);
    return v;
}
__device__ __forceinline__ float warp_max(float v) {
#pragma unroll
    for (int m = 16; m > 0; m >>= 1) v = fmaxf(v, __shfl_xor_sync(0xffffffffu, v, m));
    return v;
}
__device__ __forceinline__ float sigf(float x) { return 1.0f / (1.0f + __expf(-x)); }

__device__ __forceinline__ unsigned long long fma2(unsigned long long a,
                                                   unsigned long long b,
                                                   unsigned long long c) {
    unsigned long long d;
    asm("fma.rn.f32x2 %0, %1, %2, %3;" : "=l"(d) : "l"(a), "l"(b), "l"(c));
    return d;
}
__device__ __forceinline__ float2 unpack2(unsigned long long v) {
    unsigned int lo, hi;
    asm("mov.b64 {%0, %1}, %2;" : "=r"(lo), "=r"(hi) : "l"(v));
    return make_float2(__uint_as_float(lo), __uint_as_float(hi));
}

__device__ __forceinline__ void gsync() {
    __syncthreads();
    if (threadIdx.x == 0) {
        __threadfence();
        volatile unsigned* vg = &g_gen;
        unsigned my = *vg;
        if (atomicAdd(&g_cnt, 1u) == NBLK - 1u) {
            atomicExch(&g_cnt, 0u);
            __threadfence();
            *vg = my + 1u;
        } else {
            while (*vg == my) { }
        }
        __threadfence();
    }
    __syncthreads();
}

// ---------------- prep kernels ----------------
__global__ void __launch_bounds__(256) kprep_w(const float* __restrict__ W_ih,
                                               const float* __restrict__ W_hh,
                                               const float* __restrict__ phi_w) {
    int idx = blockIdx.x * blockDim.x + threadIdx.x;
    int stride = gridDim.x * blockDim.x;
    for (int i = idx; i < KP2 * MPAD; i += stride) {
        int k = i / MPAD, r = i % MPAD;
        float v = 0.0f;
        if (r < MROWS) {
            if (k < VALD)            v = W_ih[r * (EMB + VALD) + EMB + k];
            else if (k < VALD + HID) v = W_hh[r * HID + (k - VALD)];
        }
        g_Wdup[(size_t)k * (2 * MPAD) + 2 * r]     = v;
        g_Wdup[(size_t)k * (2 * MPAD) + 2 * r + 1] = v;
    }
    for (int i = idx; i < KEY * HIDP; i += stride) {
        int kq = i / HIDP, j = i % HIDP;
        g_phiH[i] = (j < HID) ? __float2half(phi_w[kq * HID + j]) : __half(0.0f);
    }
    for (int i = idx; i < (KP2 - (VALD + HID)) * BB; i += stride)
        g_Z[(VALD + HID) * BB + i] = 0.0f;
}

__global__ void __launch_bounds__(256) kprep_vocab(const float* __restrict__ W_ih,
                                                   const float* __restrict__ embedding,
                                                   const float* __restrict__ b_ih,
                                                   const float* __restrict__ b_hh) {
    __shared__ float emb[EMB];
    int v = blockIdx.x;
    for (int e = threadIdx.x; e < EMB; e += 256) emb[e] = embedding[v * EMB + e];
    __syncthreads();
    for (int r = threadIdx.x; r < MPAD; r += 256) {
        float s = 0.0f;
        if (r < MROWS) {
            s = b_ih[r] + b_hh[r];
            const float* wr = &W_ih[(size_t)r * (EMB + VALD)];
#pragma unroll 4
            for (int e = 0; e < EMB; e++) s += wr[e] * emb[e];
        }
        g_gv[v * MPAD + r] = s;
    }
}

__global__ void __launch_bounds__(256) kprep_keys(const float* __restrict__ keys) {
    __shared__ float ts[64][129];
    int s0 = blockIdx.x * 64;
    int b  = blockIdx.y;
    int tid = threadIdx.x;
#pragma unroll
    for (int p = 0; p < 8; p++) {
        int i  = p * 8 + (tid >> 5);
        int k4 = (tid & 31) * 4;
        float4 v = *(const float4*)&keys[((size_t)(s0 + i) * BB + b) * KEY + k4];
        ts[i][k4] = v.x; ts[i][k4 + 1] = v.y; ts[i][k4 + 2] = v.z; ts[i][k4 + 3] = v.w;
    }
    __syncthreads();
#pragma unroll
    for (int p = 0; p < 8; p++) {
        int k  = p * 16 + (tid >> 4);
        int s4 = (tid & 15) * 4;
        __half2 a = __floats2half2_rn(ts[s4][k],     ts[s4 + 1][k]);
        __half2 c = __floats2half2_rn(ts[s4 + 2][k], ts[s4 + 3][k]);
        __half2* dst = (__half2*)&g_keysH[((size_t)b * KEY + k) * SS + s0 + s4];
        dst[0] = a; dst[1] = c;
    }
}

__global__ void __launch_bounds__(256) kprep_vals(const float* __restrict__ values) {
    int s0 = blockIdx.x * 64;
    int b  = blockIdx.y;
    int tid = threadIdx.x;
#pragma unroll
    for (int p = 0; p < 8; p++) {
        int e = p * 256 + tid;
        int row = e >> 5;
        int c4 = (e & 31) * 4;
        float4 v = *(const float4*)&values[((size_t)(s0 + row) * BB + b) * VALD + c4];
        *(float4*)&g_valsT[((size_t)b * SS + s0 + row) * VALD + c4] = v;
    }
}

// ---------------- attention ----------------
__device__ void attention(int b, int tid,
                          const float* __restrict__ phi_b,
                          const float* h_s, float* q_s, float* qp,
                          float* e_s, float* e4, float* part,
                          float* ctx_s, float* red_s) {
    int warp = tid >> 5, lane = tid & 31;

    // q[kq] = phi(kq,:) . h + phi_b[kq]   (fp16 phi, uint4 loads; 2 j-halves)
    {
        int kq = tid & 127;
        int hf = tid >> 7;
        const uint4* pw = (const uint4*)&g_phiH[kq * HIDP + hf * (HIDP / 2)];
        const float* hh = &h_s[hf * (HIDP / 2)];
        float acc = 0.0f;
#pragma unroll
        for (int u = 0; u < HIDP / 16; u++) {          // 19
            uint4 raw = pw[u];
            float2 f0 = __half22float2(*(const __half2*)&raw.x);
            float2 f1 = __half22float2(*(const __half2*)&raw.y);
            float2 f2 = __half22float2(*(const __half2*)&raw.z);
            float2 f3 = __half22float2(*(const __half2*)&raw.w);
            const float* hb = &hh[u * 8];
            acc = fmaf(f0.x, hb[0], acc); acc = fmaf(f0.y, hb[1], acc);
            acc = fmaf(f1.x, hb[2], acc); acc = fmaf(f1.y, hb[3], acc);
            acc = fmaf(f2.x, hb[4], acc); acc = fmaf(f2.y, hb[5], acc);
            acc = fmaf(f3.x, hb[6], acc); acc = fmaf(f3.y, hb[7], acc);
        }
        qp[tid] = acc;
    }
    __syncthreads();
    if (tid < KEY) q_s[tid] = qp[tid] + qp[tid + 128] + phi_b[tid];
    __syncthreads();

    // energy: thread = (kg 0..3, sg 0..63): 32 k x 8 s, fp16 keys via LDG.128
    {
        int kg = tid >> 6;
        int sg = tid & 63;
        const uint4* kp = (const uint4*)&g_keysH[((size_t)b * KEY + kg * 32) * SS + sg * 8];
        float a0 = 0, a1 = 0, a2 = 0, a3 = 0, a4 = 0, a5 = 0, a6 = 0, a7 = 0;
#pragma unroll 8
        for (int k = 0; k < 32; k++) {
            uint4 raw = kp[(size_t)k * (SS / 8)];
            float qk = q_s[kg * 32 + k];
            float2 f0 = __half22float2(*(const __half2*)&raw.x);
            float2 f1 = __half22float2(*(const __half2*)&raw.y);
            float2 f2 = __half22float2(*(const __half2*)&raw.z);
            float2 f3 = __half22float2(*(const __half2*)&raw.w);
            a0 = fmaf(qk, f0.x, a0); a1 = fmaf(qk, f0.y, a1);
            a2 = fmaf(qk, f1.x, a2); a3 = fmaf(qk, f1.y, a3);
            a4 = fmaf(qk, f2.x, a4); a5 = fmaf(qk, f2.y, a5);
            a6 = fmaf(qk, f3.x, a6); a7 = fmaf(qk, f3.y, a7);
        }
        *(float4*)&e4[kg * SS + sg * 8]     = make_float4(a0, a1, a2, a3);
        *(float4*)&e4[kg * SS + sg * 8 + 4] = make_float4(a4, a5, a6, a7);
    }
    __syncthreads();
    for (int s = tid; s < SS; s += 256)
        e_s[s] = e4[s] + e4[SS + s] + e4[2 * SS + s] + e4[3 * SS + s];
    __syncthreads();

    // softmax
    float m = -3.0e38f;
    for (int s = tid; s < SS; s += 256) m = fmaxf(m, e_s[s]);
    m = warp_max(m);
    if (lane == 0) red_s[warp] = m;
    __syncthreads();
    float mf = red_s[0];
#pragma unroll
    for (int i = 1; i < 8; i++) mf = fmaxf(mf, red_s[i]);
    __syncthreads();
    float sum = 0.0f;
    for (int s = tid; s < SS; s += 256) {
        float v = __expf(e_s[s] - mf);
        e_s[s] = v;
        sum += v;
    }
    sum = warp_sum(sum);
    if (lane == 0) red_s[warp] = sum;
    __syncthreads();
    float tot = red_s[0];
#pragma unroll
    for (int i = 1; i < 8; i++) tot += red_s[i];
    float inv = 1.0f / tot;
    for (int s = tid; s < SS; s += 256) e_s[s] *= inv;
    __syncthreads();

    // ctx: warp w: s in [w*64,(w+1)*64), lane owns 4 d (float4)
    {
        float4 acc = make_float4(0, 0, 0, 0);
        int sbase = warp * 64;
        const float4* vp = (const float4*)&g_valsT[((size_t)b * SS + sbase) * VALD + lane * 4];
#pragma unroll 8
        for (int i = 0; i < 64; i++) {
            float a = e_s[sbase + i];
            float4 vv = vp[(size_t)i * (VALD / 4)];
            acc.x = fmaf(a, vv.x, acc.x);
            acc.y = fmaf(a, vv.y, acc.y);
            acc.z = fmaf(a, vv.z, acc.z);
            acc.w = fmaf(a, vv.w, acc.w);
        }
        *(float4*)&part[warp * VALD + lane * 4] = acc;
    }
    __syncthreads();
    if (tid < VALD) {
        float s = 0.0f;
#pragma unroll
        for (int w = 0; w < 8; w++) s += part[w * VALD + tid];
        ctx_s[tid] = s;
    }
    __syncthreads();
}

// ---------------- persistent main kernel ----------------
__global__ void __launch_bounds__(256, 2) kmain(const int* __restrict__ input,
                                                const float* __restrict__ phi_b,
                                                const float* __restrict__ h0,
                                                const float* __restrict__ c0,
                                                const float* __restrict__ proj_w,
                                                const float* __restrict__ proj_b,
                                                float* __restrict__ out) {
    __shared__ float h_s[HIDP];
    __shared__ float q_s[KEY];
    __shared__ float qp[256];
    __shared__ float e_s[SS];
    __shared__ __align__(16) float e4[4 * SS];
    __shared__ __align__(16) float part[8 * VALD];
    __shared__ float ctx_s[VALD];
    __shared__ float ctxo_s[VALD];
    __shared__ float red_s[8];
    __shared__ __align__(16) float Ws[16 * 64];
    __shared__ __align__(16) float Zs[16 * 64];

    int bid = blockIdx.x, tid = threadIdx.x;
    int warp = tid >> 5, lane = tid & 31;
    int b = bid;

    for (int j = tid; j < HIDP; j += 256) {
        h_s[j] = (j < HID) ? h0[j] : 0.0f;
        if (j < HID) g_c[b * HID + j] = c0[j];
    }
    __syncthreads();
    attention(b, tid, phi_b, h_s, q_s, qp, e_s, e4, part, ctx_s, red_s);
    for (int d = tid; d < VALD; d += 256) g_Z[d * BB + b] = ctx_s[d];
    for (int j = tid; j < HID; j += 256)  g_Z[(VALD + j) * BB + b] = h_s[j];
    gsync();

    for (int t = 0; t < TT; t++) {
        // ---- GEMM phase: 152 tiles of 32r x 64c ----
        if (bid < GTILES) {
            int rowBase = (bid % 38) * 32;
            int colBase = (bid / 38) * 64;
            int rg = tid & 15, cg = tid >> 4;
            int sk = tid >> 4, soff = (tid & 15) * 4;

            float4 wbuf = *(const float4*)&g_Wdup[(size_t)sk * (2 * MPAD) + rowBase * 2 + soff];
            float4 zbuf = *(const float4*)&g_Z[sk * BB + colBase + soff];

            unsigned long long a00 = 0, a01 = 0, a10 = 0, a11 = 0;
            const int NKT = KP2 / 16;
            for (int kt = 0; kt < NKT; kt++) {
                __syncthreads();
                *(float4*)&Ws[sk * 64 + soff] = wbuf;
                *(float4*)&Zs[sk * 64 + soff] = zbuf;
                __syncthreads();
                if (kt + 1 < NKT) {
                    int kb = (kt + 1) * 16;
                    wbuf = *(const float4*)&g_Wdup[(size_t)(kb + sk) * (2 * MPAD) + rowBase * 2 + soff];
                    zbuf = *(const float4*)&g_Z[(kb + sk) * BB + colBase + soff];
                }
#pragma unroll
                for (int k = 0; k < 16; k++) {
                    ulonglong2 ww = *(const ulonglong2*)&Ws[k * 64 + rg * 4];
                    ulonglong2 zz = *(const ulonglong2*)&Zs[k * 64 + cg * 4];
                    a00 = fma2(ww.x, zz.x, a00);
                    a01 = fma2(ww.x, zz.y, a01);
                    a10 = fma2(ww.y, zz.x, a10);
                    a11 = fma2(ww.y, zz.y, a11);
                }
            }
            float2 v00 = unpack2(a00), v01 = unpack2(a01);
            float2 v10 = unpack2(a10), v11 = unpack2(a11);
            int r = rowBase + rg * 2;
            int c = colBase + cg * 4;
            *(float2*)&g_gmm[(size_t)(c + 0) * MPAD + r] = make_float2(v00.x, v10.x);
            *(float2*)&g_gmm[(size_t)(c + 1) * MPAD + r] = make_float2(v00.y, v10.y);
            *(float2*)&g_gmm[(size_t)(c + 2) * MPAD + r] = make_float2(v01.x, v11.x);
            *(float2*)&g_gmm[(size_t)(c + 3) * MPAD + r] = make_float2(v01.y, v11.y);
        }
        gsync();

        // ---- per-batch phase ----
        int tok = input[t * BB + b];
        for (int d = tid; d < VALD; d += 256) ctxo_s[d] = g_Z[d * BB + b];

        const float* gm = &g_gmm[(size_t)b * MPAD];
        const float* gv = &g_gv[(size_t)tok * MPAD];
        for (int j = tid; j < HID; j += 256) {
            float gi = gm[j]           + gv[j];
            float gf = gm[HID + j]     + gv[HID + j];
            float gg = gm[2 * HID + j] + gv[2 * HID + j];
            float go = gm[3 * HID + j] + gv[3 * HID + j];
            float cc = sigf(gf) * g_c[b * HID + j] + sigf(gi) * tanhf(gg);
            float hh = sigf(go) * tanhf(cc);
            g_c[b * HID + j] = cc;
            h_s[j] = hh;
        }
        __syncthreads();

        for (int v = warp; v < VOCAB; v += 8) {
            float s = 0.0f;
            for (int j = lane; j < HID + VALD; j += 32) {
                float x = (j < HID) ? h_s[j] : ctxo_s[j - HID];
                s = fmaf(proj_w[v * (HID + VALD) + j], x, s);
            }
            s = warp_sum(s);
            if (lane == 0) out[((size_t)t * BB + b) * VOCAB + v] = s + proj_b[v];
        }

        attention(b, tid, phi_b, h_s, q_s, qp, e_s, e4, part, ctx_s, red_s);

        for (int d = tid; d < VALD; d += 256) g_Z[d * BB + b] = ctx_s[d];
        for (int j = tid; j < HID; j += 256)  g_Z[(VALD + j) * BB + b] = h_s[j];
        gsync();
    }
}

// ---------------- launch ----------------
extern "C" void kernel_launch(void* const* d_in, const int* in_sizes, int n_in,
                              void* d_out, int out_size) {
    const int*   input     = (const int*)  d_in[0];
    const float* keys      = (const float*)d_in[1];
    const float* values    = (const float*)d_in[2];
    const float* embedding = (const float*)d_in[3];
    const float* phi_w     = (const float*)d_in[4];
    const float* phi_b     = (const float*)d_in[5];
    const float* h0        = (const float*)d_in[6];
    const float* c0        = (const float*)d_in[7];
    const float* W_ih      = (const float*)d_in[8];
    const float* b_ih      = (const float*)d_in[9];
    const float* W_hh      = (const float*)d_in[10];
    const float* b_hh      = (const float*)d_in[11];
    const float* proj_w    = (const float*)d_in[12];
    const float* proj_b    = (const float*)d_in[13];
    float* out = (float*)d_out;

    kprep_w<<<512, 256>>>(W_ih, W_hh, phi_w);
    kprep_vocab<<<VOCAB, 256>>>(W_ih, embedding, b_ih, b_hh);
    kprep_keys<<<dim3(8, BB), 256>>>(keys);
    kprep_vals<<<dim3(8, BB), 256>>>(values);
    kmain<<<NBLK, 256>>>(input, phi_b, h0, c0, proj_w, proj_b, out);
}

// round 5
// speedup vs baseline: 3.0585x; 1.3238x over previous
#include <cuda_runtime.h>
#include <cuda_fp16.h>

#define EMB   400
#define HID   300
#define HIDP  304
#define KEY   128
#define VALD  128
#define VOCAB 33
#define TT    256
#define BB    256
#define SS    512

#define KP2   432          // GEMM K: ctx(128) + h(300) + pad(4)
#define MROWS 1200
#define MPAD  1216
#define NBLK  256
#define KTSPLIT 18         // k-tile split point (18*16 = 288)
#define NKT   27           // total k-tiles (27*16 = 432)

// ---------------- device scratch ----------------
__device__ float  g_Wdup[(size_t)KP2 * 2 * MPAD];
__device__ float  g_Z[KP2 * BB];
__device__ float  g_gmm[BB * MPAD];
__device__ float  g_gmm2[BB * MPAD];                      // K-split upper partial
__device__ float  g_c[BB * HID];
__device__ float  g_gv[VOCAB * MPAD];
__device__ __half g_phiH[KEY * HIDP];
__device__ __half g_keysH[(size_t)BB * KEY * SS];         // [b][k][s] fp16 (33.5MB)
__device__ __half g_valsH[(size_t)BB * SS * VALD];        // [b][s][d] fp16 (33.5MB)
__device__ unsigned g_cnt;
__device__ unsigned g_gen;

// ---------------- helpers ----------------
__device__ __forceinline__ float warp_sum(float v) {
#pragma unroll
    for (int m = 16; m > 0; m >>= 1) v += __shfl_xor_sync(0xffffffffu, v, m);
    return v;
}
__device__ __forceinline__ float warp_max(float v) {
#pragma unroll
    for (int m = 16; m > 0; m >>= 1) v = fmaxf(v, __shfl_xor_sync(0xffffffffu, v, m));
    return v;
}
__device__ __forceinline__ float sigf(float x) { return 1.0f / (1.0f + __expf(-x)); }

__device__ __forceinline__ unsigned long long fma2(unsigned long long a,
                                                   unsigned long long b,
                                                   unsigned long long c) {
    unsigned long long d;
    asm("fma.rn.f32x2 %0, %1, %2, %3;" : "=l"(d) : "l"(a), "l"(b), "l"(c));
    return d;
}
__device__ __forceinline__ float2 unpack2(unsigned long long v) {
    unsigned int lo, hi;
    asm("mov.b64 {%0, %1}, %2;" : "=r"(lo), "=r"(hi) : "l"(v));
    return make_float2(__uint_as_float(lo), __uint_as_float(hi));
}

__device__ __forceinline__ void gsync() {
    __syncthreads();
    if (threadIdx.x == 0) {
        __threadfence();
        volatile unsigned* vg = &g_gen;
        unsigned my = *vg;
        if (atomicAdd(&g_cnt, 1u) == NBLK - 1u) {
            atomicExch(&g_cnt, 0u);
            __threadfence();
            *vg = my + 1u;
        } else {
            while (*vg == my) { }
        }
        __threadfence();
    }
    __syncthreads();
}

// ---------------- prep kernels ----------------
__global__ void __launch_bounds__(256) kprep_w(const float* __restrict__ W_ih,
                                               const float* __restrict__ W_hh,
                                               const float* __restrict__ phi_w) {
    int idx = blockIdx.x * blockDim.x + threadIdx.x;
    int stride = gridDim.x * blockDim.x;
    for (int i = idx; i < KP2 * MPAD; i += stride) {
        int k = i / MPAD, r = i % MPAD;
        float v = 0.0f;
        if (r < MROWS) {
            if (k < VALD)            v = W_ih[r * (EMB + VALD) + EMB + k];
            else if (k < VALD + HID) v = W_hh[r * HID + (k - VALD)];
        }
        g_Wdup[(size_t)k * (2 * MPAD) + 2 * r]     = v;
        g_Wdup[(size_t)k * (2 * MPAD) + 2 * r + 1] = v;
    }
    for (int i = idx; i < KEY * HIDP; i += stride) {
        int kq = i / HIDP, j = i % HIDP;
        g_phiH[i] = (j < HID) ? __float2half(phi_w[kq * HID + j]) : __half(0.0f);
    }
    for (int i = idx; i < (KP2 - (VALD + HID)) * BB; i += stride)
        g_Z[(VALD + HID) * BB + i] = 0.0f;
    for (int i = idx; i < BB * MPAD; i += stride)
        g_gmm2[i] = 0.0f;
}

__global__ void __launch_bounds__(256) kprep_vocab(const float* __restrict__ W_ih,
                                                   const float* __restrict__ embedding,
                                                   const float* __restrict__ b_ih,
                                                   const float* __restrict__ b_hh) {
    __shared__ float emb[EMB];
    int v = blockIdx.x;
    for (int e = threadIdx.x; e < EMB; e += 256) emb[e] = embedding[v * EMB + e];
    __syncthreads();
    for (int r = threadIdx.x; r < MPAD; r += 256) {
        float s = 0.0f;
        if (r < MROWS) {
            s = b_ih[r] + b_hh[r];
            const float* wr = &W_ih[(size_t)r * (EMB + VALD)];
#pragma unroll 4
            for (int e = 0; e < EMB; e++) s += wr[e] * emb[e];
        }
        g_gv[v * MPAD + r] = s;
    }
}

__global__ void __launch_bounds__(256) kprep_keys(const float* __restrict__ keys) {
    __shared__ float ts[64][129];
    int s0 = blockIdx.x * 64;
    int b  = blockIdx.y;
    int tid = threadIdx.x;
#pragma unroll
    for (int p = 0; p < 8; p++) {
        int i  = p * 8 + (tid >> 5);
        int k4 = (tid & 31) * 4;
        float4 v = *(const float4*)&keys[((size_t)(s0 + i) * BB + b) * KEY + k4];
        ts[i][k4] = v.x; ts[i][k4 + 1] = v.y; ts[i][k4 + 2] = v.z; ts[i][k4 + 3] = v.w;
    }
    __syncthreads();
#pragma unroll
    for (int p = 0; p < 8; p++) {
        int k  = p * 16 + (tid >> 4);
        int s4 = (tid & 15) * 4;
        __half2 a = __floats2half2_rn(ts[s4][k],     ts[s4 + 1][k]);
        __half2 c = __floats2half2_rn(ts[s4 + 2][k], ts[s4 + 3][k]);
        __half2* dst = (__half2*)&g_keysH[((size_t)b * KEY + k) * SS + s0 + s4];
        dst[0] = a; dst[1] = c;
    }
}

__global__ void __launch_bounds__(256) kprep_vals(const float* __restrict__ values) {
    int s0 = blockIdx.x * 64;
    int b  = blockIdx.y;
    int tid = threadIdx.x;
#pragma unroll
    for (int p = 0; p < 4; p++) {
        int item = p * 256 + tid;       // 1024 items: 64 rows x 16 d-groups
        int row = item >> 4;
        int g   = item & 15;
        const float4* src = (const float4*)&values[((size_t)(s0 + row) * BB + b) * VALD + g * 8];
        float4 v0 = src[0], v1 = src[1];
        __half2 h0 = __floats2half2_rn(v0.x, v0.y);
        __half2 h1 = __floats2half2_rn(v0.z, v0.w);
        __half2 h2 = __floats2half2_rn(v1.x, v1.y);
        __half2 h3 = __floats2half2_rn(v1.z, v1.w);
        *(uint4*)&g_valsH[((size_t)b * SS + s0 + row) * VALD + g * 8] =
            make_uint4(*(unsigned*)&h0, *(unsigned*)&h1, *(unsigned*)&h2, *(unsigned*)&h3);
    }
}

// ---------------- attention ----------------
__device__ void attention(int b, int tid,
                          const float* __restrict__ phi_b,
                          const float* h_s, float* q_s, float* qp,
                          float* e_s, float* e4, float* part,
                          float* ctx_s, float* red_s) {
    int warp = tid >> 5, lane = tid & 31;

    // q[kq] = phi(kq,:) . h + phi_b[kq]
    {
        int kq = tid & 127;
        int hf = tid >> 7;
        const uint4* pw = (const uint4*)&g_phiH[kq * HIDP + hf * (HIDP / 2)];
        const float* hh = &h_s[hf * (HIDP / 2)];
        float acc = 0.0f;
#pragma unroll
        for (int u = 0; u < HIDP / 16; u++) {
            uint4 raw = pw[u];
            float2 f0 = __half22float2(*(const __half2*)&raw.x);
            float2 f1 = __half22float2(*(const __half2*)&raw.y);
            float2 f2 = __half22float2(*(const __half2*)&raw.z);
            float2 f3 = __half22float2(*(const __half2*)&raw.w);
            const float* hb = &hh[u * 8];
            acc = fmaf(f0.x, hb[0], acc); acc = fmaf(f0.y, hb[1], acc);
            acc = fmaf(f1.x, hb[2], acc); acc = fmaf(f1.y, hb[3], acc);
            acc = fmaf(f2.x, hb[4], acc); acc = fmaf(f2.y, hb[5], acc);
            acc = fmaf(f3.x, hb[6], acc); acc = fmaf(f3.y, hb[7], acc);
        }
        qp[tid] = acc;
    }
    __syncthreads();
    if (tid < KEY) q_s[tid] = qp[tid] + qp[tid + 128] + phi_b[tid];
    __syncthreads();

    // energy: thread = (kg 0..3, sg 0..63): 32 k x 8 s
    {
        int kg = tid >> 6;
        int sg = tid & 63;
        const uint4* kp = (const uint4*)&g_keysH[((size_t)b * KEY + kg * 32) * SS + sg * 8];
        float a0 = 0, a1 = 0, a2 = 0, a3 = 0, a4 = 0, a5 = 0, a6 = 0, a7 = 0;
#pragma unroll 8
        for (int k = 0; k < 32; k++) {
            uint4 raw = kp[(size_t)k * (SS / 8)];
            float qk = q_s[kg * 32 + k];
            float2 f0 = __half22float2(*(const __half2*)&raw.x);
            float2 f1 = __half22float2(*(const __half2*)&raw.y);
            float2 f2 = __half22float2(*(const __half2*)&raw.z);
            float2 f3 = __half22float2(*(const __half2*)&raw.w);
            a0 = fmaf(qk, f0.x, a0); a1 = fmaf(qk, f0.y, a1);
            a2 = fmaf(qk, f1.x, a2); a3 = fmaf(qk, f1.y, a3);
            a4 = fmaf(qk, f2.x, a4); a5 = fmaf(qk, f2.y, a5);
            a6 = fmaf(qk, f3.x, a6); a7 = fmaf(qk, f3.y, a7);
        }
        *(float4*)&e4[kg * SS + sg * 8]     = make_float4(a0, a1, a2, a3);
        *(float4*)&e4[kg * SS + sg * 8 + 4] = make_float4(a4, a5, a6, a7);
    }
    __syncthreads();
    for (int s = tid; s < SS; s += 256)
        e_s[s] = e4[s] + e4[SS + s] + e4[2 * SS + s] + e4[3 * SS + s];
    __syncthreads();

    // softmax
    float m = -3.0e38f;
    for (int s = tid; s < SS; s += 256) m = fmaxf(m, e_s[s]);
    m = warp_max(m);
    if (lane == 0) red_s[warp] = m;
    __syncthreads();
    float mf = red_s[0];
#pragma unroll
    for (int i = 1; i < 8; i++) mf = fmaxf(mf, red_s[i]);
    __syncthreads();
    float sum = 0.0f;
    for (int s = tid; s < SS; s += 256) {
        float v = __expf(e_s[s] - mf);
        e_s[s] = v;
        sum += v;
    }
    sum = warp_sum(sum);
    if (lane == 0) red_s[warp] = sum;
    __syncthreads();
    float tot = red_s[0];
#pragma unroll
    for (int i = 1; i < 8; i++) tot += red_s[i];
    float inv = 1.0f / tot;
    for (int s = tid; s < SS; s += 256) e_s[s] *= inv;
    __syncthreads();

    // ctx: warp w covers s in [w*64, w*64+64); lane: sh = lane>>4 picks 32-s half,
    // dg = lane&15 picks 8 d's (uint4 fp16 loads)
    {
        int sh = lane >> 4;
        int dg = lane & 15;
        int sbase = warp * 64 + sh * 32;
        const uint4* vp = (const uint4*)&g_valsH[((size_t)b * SS + sbase) * VALD + dg * 8];
        float a0 = 0, a1 = 0, a2 = 0, a3 = 0, a4 = 0, a5 = 0, a6 = 0, a7 = 0;
#pragma unroll 8
        for (int i = 0; i < 32; i++) {
            uint4 raw = vp[(size_t)i * (VALD / 8)];
            float w = e_s[sbase + i];
            float2 f0 = __half22float2(*(const __half2*)&raw.x);
            float2 f1 = __half22float2(*(const __half2*)&raw.y);
            float2 f2 = __half22float2(*(const __half2*)&raw.z);
            float2 f3 = __half22float2(*(const __half2*)&raw.w);
            a0 = fmaf(w, f0.x, a0); a1 = fmaf(w, f0.y, a1);
            a2 = fmaf(w, f1.x, a2); a3 = fmaf(w, f1.y, a3);
            a4 = fmaf(w, f2.x, a4); a5 = fmaf(w, f2.y, a5);
            a6 = fmaf(w, f3.x, a6); a7 = fmaf(w, f3.y, a7);
        }
        int prow = warp * 2 + sh;
        *(float4*)&part[prow * VALD + dg * 8]     = make_float4(a0, a1, a2, a3);
        *(float4*)&part[prow * VALD + dg * 8 + 4] = make_float4(a4, a5, a6, a7);
    }
    __syncthreads();
    if (tid < VALD) {
        float s = 0.0f;
#pragma unroll
        for (int w = 0; w < 16; w++) s += part[w * VALD + tid];
        ctx_s[tid] = s;
    }
    __syncthreads();
}

// ---------------- persistent main kernel ----------------
__global__ void __launch_bounds__(256, 2) kmain(const int* __restrict__ input,
                                                const float* __restrict__ phi_b,
                                                const float* __restrict__ h0,
                                                const float* __restrict__ c0,
                                                const float* __restrict__ proj_w,
                                                const float* __restrict__ proj_b,
                                                float* __restrict__ out) {
    __shared__ float h_s[HIDP];
    __shared__ float q_s[KEY];
    __shared__ float qp[256];
    __shared__ float e_s[SS];
    __shared__ __align__(16) float e4[4 * SS];
    __shared__ __align__(16) float part[16 * VALD];
    __shared__ float ctx_s[VALD];
    __shared__ float ctxo_s[VALD];
    __shared__ float red_s[8];
    __shared__ __align__(16) float Ws[16 * 64];
    __shared__ __align__(16) float Zs[16 * 64];

    int bid = blockIdx.x, tid = threadIdx.x;
    int warp = tid >> 5, lane = tid & 31;
    int b = bid;

    // GEMM role (fixed per block)
    int gT, gkt0, gkt1;
    bool gLower = (bid < 152);
    if (gLower) { gT = bid; gkt0 = 0; gkt1 = (gT < 104) ? KTSPLIT : NKT; }
    else        { gT = bid - 152; gkt0 = KTSPLIT; gkt1 = NKT; }
    int rowBase = (gT % 38) * 32;
    int colBase = (gT / 38) * 64;

    for (int j = tid; j < HIDP; j += 256) {
        h_s[j] = (j < HID) ? h0[j] : 0.0f;
        if (j < HID) g_c[b * HID + j] = c0[j];
    }
    __syncthreads();
    attention(b, tid, phi_b, h_s, q_s, qp, e_s, e4, part, ctx_s, red_s);
    for (int d = tid; d < VALD; d += 256) g_Z[d * BB + b] = ctx_s[d];
    for (int j = tid; j < HID; j += 256)  g_Z[(VALD + j) * BB + b] = h_s[j];
    gsync();

    for (int t = 0; t < TT; t++) {
        // ---- GEMM phase: K-split tiles, all 256 blocks active ----
        {
            int rg = tid & 15, cg = tid >> 4;
            int sk = tid >> 4, soff = (tid & 15) * 4;

            float4 wbuf = *(const float4*)&g_Wdup[(size_t)(gkt0 * 16 + sk) * (2 * MPAD) + rowBase * 2 + soff];
            float4 zbuf = *(const float4*)&g_Z[(gkt0 * 16 + sk) * BB + colBase + soff];

            unsigned long long a00 = 0, a01 = 0, a10 = 0, a11 = 0;
            for (int kt = gkt0; kt < gkt1; kt++) {
                __syncthreads();
                *(float4*)&Ws[sk * 64 + soff] = wbuf;
                *(float4*)&Zs[sk * 64 + soff] = zbuf;
                __syncthreads();
                if (kt + 1 < gkt1) {
                    int kb = (kt + 1) * 16;
                    wbuf = *(const float4*)&g_Wdup[(size_t)(kb + sk) * (2 * MPAD) + rowBase * 2 + soff];
                    zbuf = *(const float4*)&g_Z[(kb + sk) * BB + colBase + soff];
                }
#pragma unroll
                for (int k = 0; k < 16; k++) {
                    ulonglong2 ww = *(const ulonglong2*)&Ws[k * 64 + rg * 4];
                    ulonglong2 zz = *(const ulonglong2*)&Zs[k * 64 + cg * 4];
                    a00 = fma2(ww.x, zz.x, a00);
                    a01 = fma2(ww.x, zz.y, a01);
                    a10 = fma2(ww.y, zz.x, a10);
                    a11 = fma2(ww.y, zz.y, a11);
                }
            }
            float* outbuf = gLower ? g_gmm : g_gmm2;
            float2 v00 = unpack2(a00), v01 = unpack2(a01);
            float2 v10 = unpack2(a10), v11 = unpack2(a11);
            int r = rowBase + rg * 2;
            int c = colBase + cg * 4;
            *(float2*)&outbuf[(size_t)(c + 0) * MPAD + r] = make_float2(v00.x, v10.x);
            *(float2*)&outbuf[(size_t)(c + 1) * MPAD + r] = make_float2(v00.y, v10.y);
            *(float2*)&outbuf[(size_t)(c + 2) * MPAD + r] = make_float2(v01.x, v11.x);
            *(float2*)&outbuf[(size_t)(c + 3) * MPAD + r] = make_float2(v01.y, v11.y);
        }
        gsync();

        // ---- per-batch phase ----
        int tok = input[t * BB + b];
        for (int d = tid; d < VALD; d += 256) ctxo_s[d] = g_Z[d * BB + b];

        const float* gm  = &g_gmm[(size_t)b * MPAD];
        const float* gm2 = &g_gmm2[(size_t)b * MPAD];
        const float* gv  = &g_gv[(size_t)tok * MPAD];
        for (int j = tid; j < HID; j += 256) {
            float gi = gm[j]           + gm2[j]           + gv[j];
            float gf = gm[HID + j]     + gm2[HID + j]     + gv[HID + j];
            float gg = gm[2 * HID + j] + gm2[2 * HID + j] + gv[2 * HID + j];
            float go = gm[3 * HID + j] + gm2[3 * HID + j] + gv[3 * HID + j];
            float cc = sigf(gf) * g_c[b * HID + j] + sigf(gi) * tanhf(gg);
            float hh = sigf(go) * tanhf(cc);
            g_c[b * HID + j] = cc;
            h_s[j] = hh;
        }
        __syncthreads();

        for (int v = warp; v < VOCAB; v += 8) {
            float s = 0.0f;
            for (int j = lane; j < HID + VALD; j += 32) {
                float x = (j < HID) ? h_s[j] : ctxo_s[j - HID];
                s = fmaf(proj_w[v * (HID + VALD) + j], x, s);
            }
            s = warp_sum(s);
            if (lane == 0) out[((size_t)t * BB + b) * VOCAB + v] = s + proj_b[v];
        }

        attention(b, tid, phi_b, h_s, q_s, qp, e_s, e4, part, ctx_s, red_s);

        for (int d = tid; d < VALD; d += 256) g_Z[d * BB + b] = ctx_s[d];
        for (int j = tid; j < HID; j += 256)  g_Z[(VALD + j) * BB + b] = h_s[j];
        gsync();
    }
}

// ---------------- launch ----------------
extern "C" void kernel_launch(void* const* d_in, const int* in_sizes, int n_in,
                              void* d_out, int out_size) {
    const int*   input     = (const int*)  d_in[0];
    const float* keys      = (const float*)d_in[1];
    const float* values    = (const float*)d_in[2];
    const float* embedding = (const float*)d_in[3];
    const float* phi_w     = (const float*)d_in[4];
    const float* phi_b     = (const float*)d_in[5];
    const float* h0        = (const float*)d_in[6];
    const float* c0        = (const float*)d_in[7];
    const float* W_ih      = (const float*)d_in[8];
    const float* b_ih      = (const float*)d_in[9];
    const float* W_hh      = (const float*)d_in[10];
    const float* b_hh      = (const float*)d_in[11];
    const float* proj_w    = (const float*)d_in[12];
    const float* proj_b    = (const float*)d_in[13];
    float* out = (float*)d_out;

    kprep_w<<<512, 256>>>(W_ih, W_hh, phi_w);
    kprep_vocab<<<VOCAB, 256>>>(W_ih, embedding, b_ih, b_hh);
    kprep_keys<<<dim3(8, BB), 256>>>(keys);
    kprep_vals<<<dim3(8, BB), 256>>>(values);
    kmain<<<NBLK, 256>>>(input, phi_b, h0, c0, proj_w, proj_b, out);
}

// round 7
// speedup vs baseline: 3.6035x; 1.1782x over previous
#include <cuda_runtime.h>
#include <cuda_fp16.h>

#define EMB   400
#define HID   300
#define HIDP  304
#define PHIS  312          // phi smem row stride (halves): odd 16B-groups -> conflict-free
#define KEY   128
#define VALD  128
#define VOCAB 33
#define TT    256
#define BB    256
#define SS    512

#define KP2   432          // GEMM K: ctx(128) + h(300) + pad(4)
#define MROWS 1200
#define MPAD  1216         // stride of g_gv
#define MPAD2 1280         // GEMM row dim (10 x 128)
#define NBLK  256
#define NSEG  12           // K segments (36 k each)
#define SEGK  36
#define CHUNK 12           // smem staging chunk (k)
#define NPIECE 240         // 20 tiles x 12 segs

// ---------------- device scratch ----------------
__device__ float  g_Wt[(size_t)KP2 * MPAD2];              // [k][r] weights (2.2MB)
__device__ float  g_Z[KP2 * BB];                          // [k][b]
__device__ float  g_gpart[(size_t)NSEG * BB * MPAD2];     // 12 partial gate buffers (15.7MB)
__device__ float  g_c[BB * HID];
__device__ float  g_gv[VOCAB * MPAD];
__device__ __half g_phiH[KEY * HIDP];
__device__ __half g_keysH[(size_t)BB * KEY * SS];         // [b][k][s] fp16
__device__ __half g_valsH[(size_t)BB * SS * VALD];        // [b][s][d] fp16
__device__ unsigned g_cnt;
__device__ unsigned g_gen;

// ---------------- shared memory overlay ----------------
struct __align__(16) SMem {
    __half phi[KEY * PHIS];            // 79872 B
    float h_s[HIDP];
    float q_s[KEY];
    float qp[256];
    float e_s[SS];
    float ctx_s[VALD];
    float ctxo_s[VALD];
    float red_s[8];
    union {
        struct { float Ws[CHUNK * 128]; float Zs[CHUNK * 128]; } g;   // 12288 B
        float e4[4 * SS];                                             // 8192 B
        float part[16 * VALD];                                        // 8192 B
    } u;
};

// ---------------- helpers ----------------
__device__ __forceinline__ float warp_sum(float v) {
#pragma unroll
    for (int m = 16; m > 0; m >>= 1) v += __shfl_xor_sync(0xffffffffu, v, m);
    return v;
}
__device__ __forceinline__ float warp_max(float v) {
#pragma unroll
    for (int m = 16; m > 0; m >>= 1) v = fmaxf(v, __shfl_xor_sync(0xffffffffu, v, m));
    return v;
}
__device__ __forceinline__ float sigf(float x) { return 1.0f / (1.0f + __expf(-x)); }

__device__ __forceinline__ unsigned long long fma2(unsigned long long a,
                                                   unsigned long long b,
                                                   unsigned long long c) {
    unsigned long long d;
    asm("fma.rn.f32x2 %0, %1, %2, %3;" : "=l"(d) : "l"(a), "l"(b), "l"(c));
    return d;
}
__device__ __forceinline__ unsigned long long pack2(float x) {
    unsigned long long d;
    unsigned int xi = __float_as_uint(x);
    asm("mov.b64 %0, {%1, %1};" : "=l"(d) : "r"(xi));
    return d;
}
__device__ __forceinline__ float2 unpack2(unsigned long long v) {
    unsigned int lo, hi;
    asm("mov.b64 {%0, %1}, %2;" : "=r"(lo), "=r"(hi) : "l"(v));
    return make_float2(__uint_as_float(lo), __uint_as_float(hi));
}

__device__ __forceinline__ void gsync() {
    __syncthreads();
    if (threadIdx.x == 0) {
        __threadfence();
        volatile unsigned* vg = &g_gen;
        unsigned my = *vg;
        if (atomicAdd(&g_cnt, 1u) == NBLK - 1u) {
            atomicExch(&g_cnt, 0u);
            __threadfence();
            *vg = my + 1u;
        } else {
            while (*vg == my) { }
        }
        __threadfence();
    }
    __syncthreads();
}

// ---------------- prep kernels ----------------
__global__ void __launch_bounds__(256) kprep_w(const float* __restrict__ W_ih,
                                               const float* __restrict__ W_hh,
                                               const float* __restrict__ phi_w) {
    int idx = blockIdx.x * blockDim.x + threadIdx.x;
    int stride = gridDim.x * blockDim.x;
    for (size_t i = idx; i < (size_t)KP2 * MPAD2; i += stride) {
        int k = i / MPAD2, r = i % MPAD2;
        float v = 0.0f;
        if (r < MROWS) {
            if (k < VALD)            v = W_ih[r * (EMB + VALD) + EMB + k];
            else if (k < VALD + HID) v = W_hh[r * HID + (k - VALD)];
        }
        g_Wt[i] = v;
    }
    for (int i = idx; i < KEY * HIDP; i += stride) {
        int kq = i / HIDP, j = i % HIDP;
        g_phiH[i] = (j < HID) ? __float2half(phi_w[kq * HID + j]) : __half(0.0f);
    }
    for (int i = idx; i < (KP2 - (VALD + HID)) * BB; i += stride)
        g_Z[(VALD + HID) * BB + i] = 0.0f;
}

__global__ void __launch_bounds__(256) kprep_vocab(const float* __restrict__ W_ih,
                                                   const float* __restrict__ embedding,
                                                   const float* __restrict__ b_ih,
                                                   const float* __restrict__ b_hh) {
    __shared__ float emb[EMB];
    int v = blockIdx.x;
    for (int e = threadIdx.x; e < EMB; e += 256) emb[e] = embedding[v * EMB + e];
    __syncthreads();
    for (int r = threadIdx.x; r < MPAD; r += 256) {
        float s = 0.0f;
        if (r < MROWS) {
            s = b_ih[r] + b_hh[r];
            const float* wr = &W_ih[(size_t)r * (EMB + VALD)];
#pragma unroll 4
            for (int e = 0; e < EMB; e++) s += wr[e] * emb[e];
        }
        g_gv[v * MPAD + r] = s;
    }
}

__global__ void __launch_bounds__(256) kprep_keys(const float* __restrict__ keys) {
    __shared__ float ts[64][129];
    int s0 = blockIdx.x * 64;
    int b  = blockIdx.y;
    int tid = threadIdx.x;
#pragma unroll
    for (int p = 0; p < 8; p++) {
        int i  = p * 8 + (tid >> 5);
        int k4 = (tid & 31) * 4;
        float4 v = *(const float4*)&keys[((size_t)(s0 + i) * BB + b) * KEY + k4];
        ts[i][k4] = v.x; ts[i][k4 + 1] = v.y; ts[i][k4 + 2] = v.z; ts[i][k4 + 3] = v.w;
    }
    __syncthreads();
#pragma unroll
    for (int p = 0; p < 8; p++) {
        int k  = p * 16 + (tid >> 4);
        int s4 = (tid & 15) * 4;
        __half2 a = __floats2half2_rn(ts[s4][k],     ts[s4 + 1][k]);
        __half2 c = __floats2half2_rn(ts[s4 + 2][k], ts[s4 + 3][k]);
        __half2* dst = (__half2*)&g_keysH[((size_t)b * KEY + k) * SS + s0 + s4];
        dst[0] = a; dst[1] = c;
    }
}

__global__ void __launch_bounds__(256) kprep_vals(const float* __restrict__ values) {
    int s0 = blockIdx.x * 64;
    int b  = blockIdx.y;
    int tid = threadIdx.x;
#pragma unroll
    for (int p = 0; p < 4; p++) {
        int item = p * 256 + tid;
        int row = item >> 4;
        int g   = item & 15;
        const float4* src = (const float4*)&values[((size_t)(s0 + row) * BB + b) * VALD + g * 8];
        float4 v0 = src[0], v1 = src[1];
        __half2 h0 = __floats2half2_rn(v0.x, v0.y);
        __half2 h1 = __floats2half2_rn(v0.z, v0.w);
        __half2 h2 = __floats2half2_rn(v1.x, v1.y);
        __half2 h3 = __floats2half2_rn(v1.z, v1.w);
        *(uint4*)&g_valsH[((size_t)b * SS + s0 + row) * VALD + g * 8] =
            make_uint4(*(unsigned*)&h0, *(unsigned*)&h1, *(unsigned*)&h2, *(unsigned*)&h3);
    }
}

// ---------------- attention ----------------
__device__ void attention(SMem* sm, int b, int tid, const float* __restrict__ phi_b) {
    int warp = tid >> 5, lane = tid & 31;

    // q[kq] = phi(kq,:) . h + phi_b[kq]   (phi from smem)
    {
        int kq = tid & 127;
        int hf = tid >> 7;
        const uint4* pw = (const uint4*)&sm->phi[kq * PHIS + hf * (HIDP / 2)];
        const float* hh = &sm->h_s[hf * (HIDP / 2)];
        float acc = 0.0f;
#pragma unroll
        for (int u = 0; u < HIDP / 16; u++) {
            uint4 raw = pw[u];
            float2 f0 = __half22float2(*(const __half2*)&raw.x);
            float2 f1 = __half22float2(*(const __half2*)&raw.y);
            float2 f2 = __half22float2(*(const __half2*)&raw.z);
            float2 f3 = __half22float2(*(const __half2*)&raw.w);
            const float* hb = &hh[u * 8];
            acc = fmaf(f0.x, hb[0], acc); acc = fmaf(f0.y, hb[1], acc);
            acc = fmaf(f1.x, hb[2], acc); acc = fmaf(f1.y, hb[3], acc);
            acc = fmaf(f2.x, hb[4], acc); acc = fmaf(f2.y, hb[5], acc);
            acc = fmaf(f3.x, hb[6], acc); acc = fmaf(f3.y, hb[7], acc);
        }
        sm->qp[tid] = acc;
    }
    __syncthreads();
    if (tid < KEY) sm->q_s[tid] = sm->qp[tid] + sm->qp[tid + 128] + phi_b[tid];
    __syncthreads();

    // energy: thread = (kg 0..3, sg 0..63): 32 k x 8 s
    {
        int kg = tid >> 6;
        int sg = tid & 63;
        const uint4* kp = (const uint4*)&g_keysH[((size_t)b * KEY + kg * 32) * SS + sg * 8];
        float a0 = 0, a1 = 0, a2 = 0, a3 = 0, a4 = 0, a5 = 0, a6 = 0, a7 = 0;
#pragma unroll 8
        for (int k = 0; k < 32; k++) {
            uint4 raw = kp[(size_t)k * (SS / 8)];
            float qk = sm->q_s[kg * 32 + k];
            float2 f0 = __half22float2(*(const __half2*)&raw.x);
            float2 f1 = __half22float2(*(const __half2*)&raw.y);
            float2 f2 = __half22float2(*(const __half2*)&raw.z);
            float2 f3 = __half22float2(*(const __half2*)&raw.w);
            a0 = fmaf(qk, f0.x, a0); a1 = fmaf(qk, f0.y, a1);
            a2 = fmaf(qk, f1.x, a2); a3 = fmaf(qk, f1.y, a3);
            a4 = fmaf(qk, f2.x, a4); a5 = fmaf(qk, f2.y, a5);
            a6 = fmaf(qk, f3.x, a6); a7 = fmaf(qk, f3.y, a7);
        }
        *(float4*)&sm->u.e4[kg * SS + sg * 8]     = make_float4(a0, a1, a2, a3);
        *(float4*)&sm->u.e4[kg * SS + sg * 8 + 4] = make_float4(a4, a5, a6, a7);
    }
    __syncthreads();
    for (int s = tid; s < SS; s += 256)
        sm->e_s[s] = sm->u.e4[s] + sm->u.e4[SS + s] + sm->u.e4[2 * SS + s] + sm->u.e4[3 * SS + s];
    __syncthreads();

    // softmax (normalization folded into ctx reduce)
    float m = -3.0e38f;
    for (int s = tid; s < SS; s += 256) m = fmaxf(m, sm->e_s[s]);
    m = warp_max(m);
    if (lane == 0) sm->red_s[warp] = m;
    __syncthreads();
    float mf = sm->red_s[0];
#pragma unroll
    for (int i = 1; i < 8; i++) mf = fmaxf(mf, sm->red_s[i]);
    __syncthreads();
    float sum = 0.0f;
    for (int s = tid; s < SS; s += 256) {
        float v = __expf(sm->e_s[s] - mf);
        sm->e_s[s] = v;
        sum += v;
    }
    sum = warp_sum(sum);
    if (lane == 0) sm->red_s[warp] = sum;
    __syncthreads();
    float tot = sm->red_s[0];
#pragma unroll
    for (int i = 1; i < 8; i++) tot += sm->red_s[i];
    float inv = 1.0f / tot;
    __syncthreads();

    // ctx: warp w covers s in [w*64,(w+1)*64); lane: sh=lane>>4, dg=lane&15 (8 d's)
    {
        int sh = lane >> 4;
        int dg = lane & 15;
        int sbase = warp * 64 + sh * 32;
        const uint4* vp = (const uint4*)&g_valsH[((size_t)b * SS + sbase) * VALD + dg * 8];
        float a0 = 0, a1 = 0, a2 = 0, a3 = 0, a4 = 0, a5 = 0, a6 = 0, a7 = 0;
#pragma unroll 8
        for (int i = 0; i < 32; i++) {
            uint4 raw = vp[(size_t)i * (VALD / 8)];
            float w = sm->e_s[sbase + i];
            float2 f0 = __half22float2(*(const __half2*)&raw.x);
            float2 f1 = __half22float2(*(const __half2*)&raw.y);
            float2 f2 = __half22float2(*(const __half2*)&raw.z);
            float2 f3 = __half22float2(*(const __half2*)&raw.w);
            a0 = fmaf(w, f0.x, a0); a1 = fmaf(w, f0.y, a1);
            a2 = fmaf(w, f1.x, a2); a3 = fmaf(w, f1.y, a3);
            a4 = fmaf(w, f2.x, a4); a5 = fmaf(w, f2.y, a5);
            a6 = fmaf(w, f3.x, a6); a7 = fmaf(w, f3.y, a7);
        }
        int prow = warp * 2 + sh;
        *(float4*)&sm->u.part[prow * VALD + dg * 8]     = make_float4(a0, a1, a2, a3);
        *(float4*)&sm->u.part[prow * VALD + dg * 8 + 4] = make_float4(a4, a5, a6, a7);
    }
    __syncthreads();
    if (tid < VALD) {
        float s = 0.0f;
#pragma unroll
        for (int w = 0; w < 16; w++) s += sm->u.part[w * VALD + tid];
        sm->ctx_s[tid] = s * inv;
    }
    __syncthreads();
}

// ---------------- persistent main kernel ----------------
__global__ void __launch_bounds__(256, 2) kmain(const int* __restrict__ input,
                                                const float* __restrict__ phi_b,
                                                const float* __restrict__ h0,
                                                const float* __restrict__ c0,
                                                const float* __restrict__ proj_w,
                                                const float* __restrict__ proj_b,
                                                float* __restrict__ out) {
    extern __shared__ char smraw[];
    SMem* sm = (SMem*)smraw;

    int bid = blockIdx.x, tid = threadIdx.x;
    int warp = tid >> 5, lane = tid & 31;
    int b = bid;

    // load phi into smem (once, persistent)
    for (int item = tid; item < KEY * (HIDP / 8); item += 256) {
        int kq = item / (HIDP / 8);
        int u  = item % (HIDP / 8);
        *(uint4*)&sm->phi[kq * PHIS + u * 8] = *(const uint4*)&g_phiH[kq * HIDP + u * 8];
    }

    // GEMM piece assignment (locals renamed gr0/gc0 to avoid shadowing param c0)
    bool gemmOn = (bid < NPIECE);
    int gTile = bid / NSEG, gSeg = bid % NSEG;
    int rowBase = (gTile % 10) * 128;
    int colBase = (gTile / 10) * 128;
    int kBase = gSeg * SEGK;
    float* outbuf = g_gpart + (size_t)gSeg * (BB * MPAD2);
    int rg = tid & 15, cg = tid >> 4;
    int gr0 = rg * 8, gc0 = cg * 8;

    for (int j = tid; j < HIDP; j += 256) {
        sm->h_s[j] = (j < HID) ? h0[j] : 0.0f;
        if (j < HID) g_c[b * HID + j] = c0[j];
    }
    __syncthreads();
    attention(sm, b, tid, phi_b);
    for (int d = tid; d < VALD; d += 256) g_Z[d * BB + b] = sm->ctx_s[d];
    for (int j = tid; j < HID; j += 256)  g_Z[(VALD + j) * BB + b] = sm->h_s[j];
    gsync();

    for (int t = 0; t < TT; t++) {
        // ---- GEMM phase: piece = (tile, kseg); 128x128 tile, 8x8 per thread ----
        if (gemmOn) {
            unsigned long long acc[8][4];
#pragma unroll
            for (int c = 0; c < 8; c++)
#pragma unroll
                for (int r = 0; r < 4; r++) acc[c][r] = 0ull;

            float2 wpre[3], zpre[3];
#pragma unroll
            for (int i = 0; i < 3; i++) {
                int item = tid + 256 * i;
                int kk = item >> 6, off = (item & 63) * 2;
                wpre[i] = *(const float2*)&g_Wt[(size_t)(kBase + kk) * MPAD2 + rowBase + off];
                zpre[i] = *(const float2*)&g_Z[(kBase + kk) * BB + colBase + off];
            }

#pragma unroll
            for (int chunk = 0; chunk < SEGK / CHUNK; chunk++) {
                __syncthreads();
#pragma unroll
                for (int i = 0; i < 3; i++) {
                    int item = tid + 256 * i;
                    int kk = item >> 6, off = (item & 63) * 2;
                    *(float2*)&sm->u.g.Ws[kk * 128 + off] = wpre[i];
                    *(float2*)&sm->u.g.Zs[kk * 128 + off] = zpre[i];
                }
                __syncthreads();
                if (chunk + 1 < SEGK / CHUNK) {
                    int kb = kBase + (chunk + 1) * CHUNK;
#pragma unroll
                    for (int i = 0; i < 3; i++) {
                        int item = tid + 256 * i;
                        int kk = item >> 6, off = (item & 63) * 2;
                        wpre[i] = *(const float2*)&g_Wt[(size_t)(kb + kk) * MPAD2 + rowBase + off];
                        zpre[i] = *(const float2*)&g_Z[(kb + kk) * BB + colBase + off];
                    }
                }
#pragma unroll 3
                for (int kk = 0; kk < CHUNK; kk++) {
                    ulonglong2 w01 = *(const ulonglong2*)&sm->u.g.Ws[kk * 128 + gr0];
                    ulonglong2 w23 = *(const ulonglong2*)&sm->u.g.Ws[kk * 128 + gr0 + 4];
                    float4 za = *(const float4*)&sm->u.g.Zs[kk * 128 + gc0];
                    float4 zb = *(const float4*)&sm->u.g.Zs[kk * 128 + gc0 + 4];
                    unsigned long long z[8];
                    z[0] = pack2(za.x); z[1] = pack2(za.y); z[2] = pack2(za.z); z[3] = pack2(za.w);
                    z[4] = pack2(zb.x); z[5] = pack2(zb.y); z[6] = pack2(zb.z); z[7] = pack2(zb.w);
#pragma unroll
                    for (int c = 0; c < 8; c++) {
                        acc[c][0] = fma2(w01.x, z[c], acc[c][0]);
                        acc[c][1] = fma2(w01.y, z[c], acc[c][1]);
                        acc[c][2] = fma2(w23.x, z[c], acc[c][2]);
                        acc[c][3] = fma2(w23.y, z[c], acc[c][3]);
                    }
                }
            }
#pragma unroll
            for (int c = 0; c < 8; c++) {
                float2 p0 = unpack2(acc[c][0]);
                float2 p1 = unpack2(acc[c][1]);
                float2 p2 = unpack2(acc[c][2]);
                float2 p3 = unpack2(acc[c][3]);
                float* dst = &outbuf[(size_t)(colBase + gc0 + c) * MPAD2 + rowBase + gr0];
                *(float4*)dst       = make_float4(p0.x, p0.y, p1.x, p1.y);
                *(float4*)(dst + 4) = make_float4(p2.x, p2.y, p3.x, p3.y);
            }
        }
        gsync();

        // ---- per-batch phase ----
        int tok = input[t * BB + b];
        for (int d = tid; d < VALD; d += 256) sm->ctxo_s[d] = g_Z[d * BB + b];

        const float* gv = &g_gv[(size_t)tok * MPAD];
        for (int j = tid; j < HID; j += 256) {
            float gi = gv[j];
            float gf = gv[HID + j];
            float gg = gv[2 * HID + j];
            float go = gv[3 * HID + j];
#pragma unroll
            for (int s = 0; s < NSEG; s++) {
                const float* gp = &g_gpart[((size_t)s * BB + b) * MPAD2];
                gi += gp[j];
                gf += gp[HID + j];
                gg += gp[2 * HID + j];
                go += gp[3 * HID + j];
            }
            float cc = sigf(gf) * g_c[b * HID + j] + sigf(gi) * tanhf(gg);
            float hh = sigf(go) * tanhf(cc);
            g_c[b * HID + j] = cc;
            sm->h_s[j] = hh;
        }
        __syncthreads();

        for (int v = warp; v < VOCAB; v += 8) {
            float s = 0.0f;
            for (int j = lane; j < HID + VALD; j += 32) {
                float x = (j < HID) ? sm->h_s[j] : sm->ctxo_s[j - HID];
                s = fmaf(proj_w[v * (HID + VALD) + j], x, s);
            }
            s = warp_sum(s);
            if (lane == 0) out[((size_t)t * BB + b) * VOCAB + v] = s + proj_b[v];
        }

        attention(sm, b, tid, phi_b);

        for (int d = tid; d < VALD; d += 256) g_Z[d * BB + b] = sm->ctx_s[d];
        for (int j = tid; j < HID; j += 256)  g_Z[(VALD + j) * BB + b] = sm->h_s[j];
        gsync();
    }
}

// ---------------- launch ----------------
extern "C" void kernel_launch(void* const* d_in, const int* in_sizes, int n_in,
                              void* d_out, int out_size) {
    const int*   input     = (const int*)  d_in[0];
    const float* keys      = (const float*)d_in[1];
    const float* values    = (const float*)d_in[2];
    const float* embedding = (const float*)d_in[3];
    const float* phi_w     = (const float*)d_in[4];
    const float* phi_b     = (const float*)d_in[5];
    const float* h0        = (const float*)d_in[6];
    const float* c0        = (const float*)d_in[7];
    const float* W_ih      = (const float*)d_in[8];
    const float* b_ih      = (const float*)d_in[9];
    const float* W_hh      = (const float*)d_in[10];
    const float* b_hh      = (const float*)d_in[11];
    const float* proj_w    = (const float*)d_in[12];
    const float* proj_b    = (const float*)d_in[13];
    float* out = (float*)d_out;

    int smbytes = (int)sizeof(SMem);
    cudaFuncSetAttribute(kmain, cudaFuncAttributeMaxDynamicSharedMemorySize, smbytes);

    kprep_w<<<512, 256>>>(W_ih, W_hh, phi_w);
    kprep_vocab<<<VOCAB, 256>>>(W_ih, embedding, b_ih, b_hh);
    kprep_keys<<<dim3(8, BB), 256>>>(keys);
    kprep_vals<<<dim3(8, BB), 256>>>(values);
    kmain<<<NBLK, 256, smbytes>>>(input, phi_b, h0, c0, proj_w, proj_b, out);
}